// round 3
// baseline (speedup 1.0000x reference)
#include <cuda_runtime.h>
#include <math.h>

#define NN      1023
#define NLEAVES 512
#define HD      300
#define NB      900

typedef unsigned long long ull;

// ---------------- static device scratch ----------------
__device__ float g_Wxp[HD * NB];     // packed W_ix|W_fx|W_ux, [k][c]
__device__ float g_Whp[HD * NB];     // packed W_ih|W_fh|W_uh
__device__ float g_XX[NN * NB];      // x @ Wxp (raw, no bias)
__device__ float g_G[2 * 256 * NB];  // per-level child GEMM results (max 512 rows)
__device__ float g_h[NN * HD];
__device__ float g_c[NN * HD];
__device__ float g_loss[NN];
__device__ float g_logp_scratch[NN * 5];

// ---------------- f32x2 helpers ----------------
static __device__ __forceinline__ ull pack2(float x, float y) {
    ull r;
    asm("mov.b64 %0, {%1, %2};" : "=l"(r) : "f"(x), "f"(y));
    return r;
}
static __device__ __forceinline__ void unpack2(ull v, float &x, float &y) {
    asm("mov.b64 {%0, %1}, %2;" : "=f"(x), "=f"(y) : "l"(v));
}
static __device__ __forceinline__ void ffma2(ull &d, ull a, ull b) {
    asm("fma.rn.f32x2 %0, %1, %2, %0;" : "+l"(d) : "l"(a), "l"(b));
}
static __device__ __forceinline__ float sigf(float x) {
    return 1.0f / (1.0f + expf(-x));
}

// ---------------- pack weights into [300][900] strips ----------------
__global__ void pack_w(const float* __restrict__ Wix, const float* __restrict__ Wfx,
                       const float* __restrict__ Wux, const float* __restrict__ Wih,
                       const float* __restrict__ Wfh, const float* __restrict__ Wuh)
{
    int idx = blockIdx.x * blockDim.x + threadIdx.x;
    if (idx >= HD * NB) return;
    int k = idx / NB, c = idx % NB;
    int g = c / HD, j = c % HD;
    const float* wx = (g == 0) ? Wix : (g == 1) ? Wfx : Wux;
    const float* wh = (g == 0) ? Wih : (g == 1) ? Wfh : Wuh;
    g_Wxp[idx] = wx[k * HD + j];
    g_Whp[idx] = wh[k * HD + j];
}

// ---------------- gathered GEMM: out[M x 900] = gather(src,rowIdx)[M x 300] @ B ---------
// mode 0: src = emb (param), B = g_Wxp, out = g_XX
// mode 1: src = g_h,         B = g_Whp, out = g_G
__global__ __launch_bounds__(256) void gemm64(const float* __restrict__ src_param,
                                              const int* __restrict__ rowIdx,
                                              int M, int mode)
{
    __shared__ float As[16][66];
    __shared__ __align__(16) float Bs[16][64];

    const float* __restrict__ src = (mode == 0) ? src_param : g_h;
    const float* __restrict__ B   = (mode == 0) ? g_Wxp : g_Whp;
    float* __restrict__ out       = (mode == 0) ? g_XX : g_G;

    const int tid = threadIdx.x;
    const int tx = tid & 15, ty = tid >> 4;
    const int m0 = blockIdx.y * 64, n0 = blockIdx.x * 64;

    // per-thread fixed A-row bases (m depends only on tid)
    int abase[4];
#pragma unroll
    for (int i = 0; i < 4; i++) {
        int m = (tid + i * 256) >> 4;
        int gm = m0 + m;
        abase[i] = (gm < M) ? rowIdx[gm] * HD : -1;
    }

    ull acc[4][2];
#pragma unroll
    for (int i = 0; i < 4; i++) { acc[i][0] = pack2(0.f, 0.f); acc[i][1] = pack2(0.f, 0.f); }

    for (int k0 = 0; k0 < HD; k0 += 16) {
#pragma unroll
        for (int i = 0; i < 4; i++) {
            int idx = tid + i * 256;
            int m = idx >> 4, k = idx & 15;
            int gk = k0 + k;
            float v = 0.f;
            if (abase[i] >= 0 && gk < HD) v = src[abase[i] + gk];
            As[k][m] = v;
        }
#pragma unroll
        for (int i = 0; i < 4; i++) {
            int idx = tid + i * 256;
            int k = idx >> 6, n = idx & 63;
            int gk = k0 + k, gn = n0 + n;
            float v = 0.f;
            if (gk < HD && gn < NB) v = B[gk * NB + gn];
            Bs[k][n] = v;
        }
        __syncthreads();

#pragma unroll
        for (int k = 0; k < 16; k++) {
            float2 b01 = *(const float2*)&Bs[k][tx * 4];
            float2 b23 = *(const float2*)&Bs[k][tx * 4 + 2];
            ull bp0 = pack2(b01.x, b01.y);
            ull bp1 = pack2(b23.x, b23.y);
#pragma unroll
            for (int i = 0; i < 4; i++) {
                float a = As[k][ty * 4 + i];
                ull ap = pack2(a, a);
                ffma2(acc[i][0], ap, bp0);
                ffma2(acc[i][1], ap, bp1);
            }
        }
        __syncthreads();
    }

#pragma unroll
    for (int i = 0; i < 4; i++) {
        int gm = m0 + ty * 4 + i;
        if (gm >= M) continue;
        float x0, x1, x2, x3;
        unpack2(acc[i][0], x0, x1);
        unpack2(acc[i][1], x2, x3);
        int gn = n0 + tx * 4;
        float* o = out + (size_t)gm * NB + gn;
        if (gn + 3 < NB) { o[0] = x0; o[1] = x1; o[2] = x2; o[3] = x3; }
        else {
            if (gn     < NB) o[0] = x0;
            if (gn + 1 < NB) o[1] = x1;
            if (gn + 2 < NB) o[2] = x2;
            if (gn + 3 < NB) o[3] = x3;
        }
    }
}

// ---------------- leaves: c = sig(i)*sig(u), h = sig(o)*tanh(c) ----------------
__global__ void leaves_kernel(const float* __restrict__ bix, const float* __restrict__ bfx,
                              const float* __restrict__ bux, const float* __restrict__ bih,
                              const float* __restrict__ bfh, const float* __restrict__ buh)
{
    int idx = blockIdx.x * blockDim.x + threadIdx.x;
    if (idx >= NLEAVES * HD) return;
    int t = idx / HD, j = idx % HD;
    const float* xx = g_XX + (size_t)t * NB;
    float i = sigf(xx[j]        + bix[j] + bih[j]);
    float o = sigf(xx[HD + j]   + bfx[j] + bfh[j]);
    float u = sigf(xx[2*HD + j] + bux[j] + buh[j]);
    float c = i * u;
    g_c[t * HD + j] = c;
    g_h[t * HD + j] = o * tanhf(c);
}

// ---------------- per-level fused LSTM cell epilogue ----------------
__global__ void level_epi(int base, int Wd, const int* __restrict__ children,
                          const float* __restrict__ bix, const float* __restrict__ bfx,
                          const float* __restrict__ bux, const float* __restrict__ bih,
                          const float* __restrict__ bfh, const float* __restrict__ buh)
{
    int idx = blockIdx.x * blockDim.x + threadIdx.x;
    if (idx >= Wd * HD) return;
    int p = idx / HD, j = idx % HD;
    int t = base + p;
    const float* xx = g_XX + (size_t)t * NB;
    const float* G0 = g_G + (size_t)(2 * p) * NB;
    const float* G1 = G0 + NB;

    float ixx = xx[j]          + bix[j];
    float fxx = xx[HD + j]     + bfx[j];
    float uxx = xx[2 * HD + j] + bux[j];
    float bf  = bfh[j];

    float g0f = G0[HD + j], g1f = G1[HD + j];

    float i = sigf(ixx + G0[j]          + G1[j]          + bih[j]);
    float o = sigf(fxx + g0f            + g1f            + bf);
    float u = sigf(uxx + G0[2 * HD + j] + G1[2 * HD + j] + buh[j]);
    float f0 = sigf(g0f + bf + fxx);
    float f1 = sigf(g1f + bf + fxx);

    int c0 = children[2 * p], c1 = children[2 * p + 1];
    float cc = i * u + f0 * g_c[c0 * HD + j] + f1 * g_c[c1 * HD + j];
    g_c[t * HD + j] = cc;
    g_h[t * HD + j] = o * tanhf(cc);
}

// ---------------- output: logits, log_softmax, per-node loss ----------------
__global__ __launch_bounds__(128) void out_kernel(const float* __restrict__ Wout,
                                                  const float* __restrict__ bout,
                                                  const int* __restrict__ labels,
                                                  float* __restrict__ out, int logp_to_out)
{
    int t = blockIdx.x;
    int tid = threadIdx.x;
    float acc[5] = {0.f, 0.f, 0.f, 0.f, 0.f};
    const float* h = g_h + (size_t)t * HD;
    for (int j = tid; j < HD; j += 128) {
        float hv = h[j];
#pragma unroll
        for (int l = 0; l < 5; l++) acc[l] += hv * Wout[j * 5 + l];
    }
#pragma unroll
    for (int off = 16; off > 0; off >>= 1) {
#pragma unroll
        for (int l = 0; l < 5; l++)
            acc[l] += __shfl_down_sync(0xffffffffu, acc[l], off);
    }
    __shared__ float s[4][5];
    int w = tid >> 5, lane = tid & 31;
    if (lane == 0) {
#pragma unroll
        for (int l = 0; l < 5; l++) s[w][l] = acc[l];
    }
    __syncthreads();
    if (tid == 0) {
        float lg[5];
#pragma unroll
        for (int l = 0; l < 5; l++)
            lg[l] = s[0][l] + s[1][l] + s[2][l] + s[3][l] + bout[l];
        float mx = lg[0];
#pragma unroll
        for (int l = 1; l < 5; l++) mx = fmaxf(mx, lg[l]);
        float se = 0.f;
#pragma unroll
        for (int l = 0; l < 5; l++) se += expf(lg[l] - mx);
        float lse = mx + logf(se);
        float* dst = logp_to_out ? (out + (size_t)t * 5) : (g_logp_scratch + (size_t)t * 5);
#pragma unroll
        for (int l = 0; l < 5; l++) dst[l] = lg[l] - lse;
        g_loss[t] = -(lg[labels[t]] - lse);
    }
}

__global__ void loss_reduce(float* __restrict__ outloss)
{
    __shared__ float s[1024];
    int tid = threadIdx.x;
    float v = 0.f;
    for (int i = tid; i < NN; i += 1024) v += g_loss[i];
    s[tid] = v;
    __syncthreads();
    for (int st = 512; st > 0; st >>= 1) {
        if (tid < st) s[tid] += s[tid + st];
        __syncthreads();
    }
    if (tid == 0) *outloss = s[0];
}

// ---------------- launch ----------------
extern "C" void kernel_launch(void* const* d_in, const int* in_sizes, int n_in,
                              void* d_out, int out_size)
{
    const int*   word_ids = (const int*)d_in[0];
    const int*   labels   = (const int*)d_in[1];
    const int*   children = (const int*)d_in[2];
    // d_in[3] children_mask: implied by tree structure (0 for leaves, 1 internal)
    const float* emb = (const float*)d_in[4];
    const float* Wix = (const float*)d_in[5],  *bix = (const float*)d_in[6];
    const float* Wih = (const float*)d_in[7],  *bih = (const float*)d_in[8];
    const float* Wfx = (const float*)d_in[9],  *bfx = (const float*)d_in[10];
    const float* Wfh = (const float*)d_in[11], *bfh = (const float*)d_in[12];
    const float* Wux = (const float*)d_in[13], *bux = (const float*)d_in[14];
    const float* Wuh = (const float*)d_in[15], *buh = (const float*)d_in[16];
    const float* Wout = (const float*)d_in[17], *bout = (const float*)d_in[18];
    float* out = (float*)d_out;

    // 1. pack weight strips
    pack_w<<<(HD * NB + 255) / 256, 256>>>(Wix, Wfx, Wux, Wih, Wfh, Wuh);

    // 2. prologue GEMM: g_XX = emb[word_ids] @ Wxp
    gemm64<<<dim3((NB + 63) / 64, (NN + 63) / 64), 256>>>(emb, word_ids, NN, 0);

    // 3. leaves (512 parallel)
    leaves_kernel<<<(NLEAVES * HD + 255) / 256, 256>>>(bix, bfx, bux, bih, bfh, buh);

    // 4. 9 sequential levels: gathered GEMM on child h rows + fused cell epilogue
    static const int bases[9]  = {512, 768, 896, 960, 992, 1008, 1016, 1020, 1022};
    static const int widths[9] = {256, 128, 64, 32, 16, 8, 4, 2, 1};
    for (int l = 0; l < 9; l++) {
        int Wd = widths[l], base = bases[l];
        int M = 2 * Wd;
        gemm64<<<dim3((NB + 63) / 64, (M + 63) / 64), 256>>>(nullptr, children + 2 * base, M, 1);
        int nth = Wd * HD;
        level_epi<<<(nth + 255) / 256, 256>>>(base, Wd, children + 2 * base,
                                              bix, bfx, bux, bih, bfh, buh);
    }

    // 5. logits + log_softmax + per-node loss
    int logp_to_out = (out_size >= NN * 5) ? 1 : 0;
    out_kernel<<<NN, 128>>>(Wout, bout, labels, out, logp_to_out);

    // 6. loss reduction into output
    if (out_size > NN * 5) {
        loss_reduce<<<1, 1024>>>(out + NN * 5);
    } else if (out_size < NN * 5) {
        loss_reduce<<<1, 1024>>>(out);
    }
}

// round 4
// speedup vs baseline: 1.6343x; 1.6343x over previous
#include <cuda_runtime.h>
#include <math.h>

#define NN      1023
#define NLEAVES 512
#define HD      300
#define GP      320          // padded per-gate width
#define NBP     960          // 3 * GP, = 15 * 64 exactly
#define NBLK    148
#define NTHR    256

typedef unsigned long long ull;

// ---------------- static device scratch ----------------
__device__ float g_Wxp[HD * NBP];     // packed W_ix|W_fx|W_ux, [k][c], gate-padded
__device__ float g_Whp[HD * NBP];     // packed W_ih|W_fh|W_uh
__device__ float g_bsum[NBP];         // b_*x + b_*h, gate-padded
__device__ float g_XX[NN * NBP];      // x @ Wxp (no bias)
__device__ float g_G[512 * NBP];      // per-level child GEMM results
__device__ float g_h[NN * HD];
__device__ float g_c[NN * HD];
__device__ float g_loss[NN];
__device__ float g_logp_scratch[NN * 5];
__device__ unsigned g_gen;            // barrier generation
__device__ unsigned g_cnt;            // barrier arrival count

// ---------------- f32x2 helpers ----------------
static __device__ __forceinline__ ull pack2(float x, float y) {
    ull r;
    asm("mov.b64 %0, {%1, %2};" : "=l"(r) : "f"(x), "f"(y));
    return r;
}
static __device__ __forceinline__ void unpack2(ull v, float &x, float &y) {
    asm("mov.b64 {%0, %1}, %2;" : "=f"(x), "=f"(y) : "l"(v));
}
static __device__ __forceinline__ void ffma2(ull &d, ull a, ull b) {
    asm("fma.rn.f32x2 %0, %1, %2, %0;" : "+l"(d) : "l"(a), "l"(b));
}
static __device__ __forceinline__ float sigf(float x) {
    return 1.0f / (1.0f + expf(-x));
}

// ---------------- software grid barrier (all NBLK blocks resident) ----------------
static __device__ __forceinline__ void gbar() {
    __syncthreads();
    if (threadIdx.x == 0) {
        __threadfence();
        unsigned gen = *((volatile unsigned*)&g_gen);
        if (atomicAdd(&g_cnt, 1u) == NBLK - 1) {
            g_cnt = 0;
            __threadfence();
            atomicAdd(&g_gen, 1u);   // release
        } else {
            while (*((volatile unsigned*)&g_gen) == gen) { }
        }
        __threadfence();
    }
    __syncthreads();
}

// ---------------- pack weights into [300][960] gate-padded strips + bias sums ------
__global__ void pack_w(const float* __restrict__ Wix, const float* __restrict__ Wfx,
                       const float* __restrict__ Wux, const float* __restrict__ Wih,
                       const float* __restrict__ Wfh, const float* __restrict__ Wuh,
                       const float* __restrict__ bix, const float* __restrict__ bfx,
                       const float* __restrict__ bux, const float* __restrict__ bih,
                       const float* __restrict__ bfh, const float* __restrict__ buh)
{
    int idx = blockIdx.x * blockDim.x + threadIdx.x;
    if (idx < HD * NBP) {
        int k = idx / NBP, c = idx % NBP;
        int g = c / GP, j = c % GP;
        float vx = 0.f, vh = 0.f;
        if (j < HD) {
            const float* wx = (g == 0) ? Wix : (g == 1) ? Wfx : Wux;
            const float* wh = (g == 0) ? Wih : (g == 1) ? Wfh : Wuh;
            vx = wx[k * HD + j];
            vh = wh[k * HD + j];
        }
        g_Wxp[idx] = vx;
        g_Whp[idx] = vh;
    }
    if (idx < NBP) {
        int g = idx / GP, j = idx % GP;
        float v = 0.f;
        if (j < HD) {
            const float* bx = (g == 0) ? bix : (g == 1) ? bfx : bux;
            const float* bh = (g == 0) ? bih : (g == 1) ? bfh : buh;
            v = bx[j] + bh[j];
        }
        g_bsum[idx] = v;
    }
}

// ---------------- tiled gathered GEMM stage (persistent-kernel device func) --------
// out[M x 960] = gather(src, rowIdx)[M x 300] @ B[300 x 960]
// 64x64 tiles, 256 threads, 4x4 microtile in f32x2, double-buffered smem.
static __device__ void gemm_stage(const float* __restrict__ src,
                                  const int* __restrict__ rowIdx, int M,
                                  const float* __restrict__ B,
                                  float* __restrict__ out,
                                  float (&As)[2][16][68],
                                  float (&Bs)[2][16][64])
{
    const int tid = threadIdx.x;
    const int tx = tid & 15, ty = tid >> 4;
    const int am  = tid & 63;        // A-load: row within tile
    const int akq = tid >> 6;        // A-load: k quad (0..3)
    const int bn4 = (tid & 15) << 2; // B-load: col within tile
    const int bk  = tid >> 4;        // B-load: k (0..15)

    const int ntm = (M + 63) >> 6;
    const int ntiles = ntm * 15;
    const int nstage = 19;           // ceil(300/16)

    for (int t = blockIdx.x; t < ntiles; t += NBLK) {
        const int m0 = (t / 15) << 6;
        const int n0 = (t % 15) << 6;

        const bool aval = (m0 + am < M);
        const int  arow = aval ? rowIdx[m0 + am] : 0;
        const float* __restrict__ aptr = src + (size_t)arow * HD + (akq << 2);
        const float* __restrict__ bptr = B + (size_t)bk * NBP + n0 + bn4;

        const bool act = (m0 + (ty << 2) < M);   // thread microtile has >=1 valid row

        float4 aReg, bReg;
        // ---- load stage 0 ----
        {
            const int kb = (akq << 2);
            if (aval) aReg = *(const float4*)(aptr);
            else      aReg = make_float4(0.f, 0.f, 0.f, 0.f);
            (void)kb;
            bReg = *(const float4*)(bptr);
        }
        As[0][(akq << 2) + 0][am] = aReg.x;
        As[0][(akq << 2) + 1][am] = aReg.y;
        As[0][(akq << 2) + 2][am] = aReg.z;
        As[0][(akq << 2) + 3][am] = aReg.w;
        *(float4*)&Bs[0][bk][bn4] = bReg;
        __syncthreads();

        ull acc[4][2];
#pragma unroll
        for (int i = 0; i < 4; i++) { acc[i][0] = pack2(0.f, 0.f); acc[i][1] = pack2(0.f, 0.f); }

        for (int s = 0; s < nstage; s++) {
            const int p = s & 1;

            // ---- prefetch stage s+1 from gmem into regs ----
            if (s + 1 < nstage) {
                const int k0 = (s + 1) << 4;
                const int kb = k0 + (akq << 2);
                if (aval && (kb + 3 < HD)) {
                    aReg = *(const float4*)(aptr + k0);
                } else {
                    aReg.x = (aval && kb + 0 < HD) ? aptr[k0 + 0] : 0.f;
                    aReg.y = (aval && kb + 1 < HD) ? aptr[k0 + 1] : 0.f;
                    aReg.z = (aval && kb + 2 < HD) ? aptr[k0 + 2] : 0.f;
                    aReg.w = (aval && kb + 3 < HD) ? aptr[k0 + 3] : 0.f;
                }
                if (k0 + bk < HD) bReg = *(const float4*)(bptr + (size_t)k0 * NBP);
                else              bReg = make_float4(0.f, 0.f, 0.f, 0.f);
            }

            // ---- compute on buffer p, distance-1 reg prefetch ----
            if (act) {
                float4 a_c = *(const float4*)&As[p][0][ty << 2];
                float4 b_c = *(const float4*)&Bs[p][0][tx << 2];
#pragma unroll
                for (int k = 0; k < 16; k++) {
                    float4 a_n = make_float4(0.f, 0.f, 0.f, 0.f);
                    float4 b_n = make_float4(0.f, 0.f, 0.f, 0.f);
                    if (k < 15) {
                        a_n = *(const float4*)&As[p][k + 1][ty << 2];
                        b_n = *(const float4*)&Bs[p][k + 1][tx << 2];
                    }
                    ull bp0 = pack2(b_c.x, b_c.y);
                    ull bp1 = pack2(b_c.z, b_c.w);
                    ull ap;
                    ap = pack2(a_c.x, a_c.x); ffma2(acc[0][0], ap, bp0); ffma2(acc[0][1], ap, bp1);
                    ap = pack2(a_c.y, a_c.y); ffma2(acc[1][0], ap, bp0); ffma2(acc[1][1], ap, bp1);
                    ap = pack2(a_c.z, a_c.z); ffma2(acc[2][0], ap, bp0); ffma2(acc[2][1], ap, bp1);
                    ap = pack2(a_c.w, a_c.w); ffma2(acc[3][0], ap, bp0); ffma2(acc[3][1], ap, bp1);
                    a_c = a_n; b_c = b_n;
                }
            }

            // ---- store prefetched regs into the other buffer ----
            if (s + 1 < nstage) {
                const int q = 1 - p;
                As[q][(akq << 2) + 0][am] = aReg.x;
                As[q][(akq << 2) + 1][am] = aReg.y;
                As[q][(akq << 2) + 2][am] = aReg.z;
                As[q][(akq << 2) + 3][am] = aReg.w;
                *(float4*)&Bs[q][bk][bn4] = bReg;
            }
            __syncthreads();
        }

        // ---- writeback ----
        if (act) {
#pragma unroll
            for (int i = 0; i < 4; i++) {
                int gm = m0 + (ty << 2) + i;
                if (gm < M) {
                    float x0, x1, x2, x3;
                    unpack2(acc[i][0], x0, x1);
                    unpack2(acc[i][1], x2, x3);
                    *(float4*)&out[(size_t)gm * NBP + n0 + (tx << 2)] =
                        make_float4(x0, x1, x2, x3);
                }
            }
        }
    }
}

// ---------------- persistent mega-kernel ----------------
__global__ __launch_bounds__(NTHR, 1) void mega_kernel(
    const int* __restrict__ word_ids, const int* __restrict__ labels,
    const int* __restrict__ children, const float* __restrict__ emb,
    const float* __restrict__ Wout, const float* __restrict__ bout,
    float* __restrict__ out, int out_size)
{
    __shared__ float As[2][16][68];
    __shared__ __align__(16) float Bs[2][16][64];
    __shared__ float sred[NTHR];

    // ---- stage 1: prologue GEMM  XX = emb[word_ids] @ Wxp ----
    gemm_stage(emb, word_ids, NN, g_Wxp, g_XX, As, Bs);
    gbar();

    // ---- stage 2: leaves (nodes 0..511) ----
    for (int idx = blockIdx.x * NTHR + threadIdx.x; idx < NLEAVES * HD; idx += NBLK * NTHR) {
        int t = idx / HD, j = idx % HD;
        const float* xx = g_XX + (size_t)t * NBP;
        float i = sigf(xx[j]          + g_bsum[j]);
        float o = sigf(xx[GP + j]     + g_bsum[GP + j]);
        float u = sigf(xx[2 * GP + j] + g_bsum[2 * GP + j]);
        float c = i * u;
        g_c[t * HD + j] = c;
        g_h[t * HD + j] = o * tanhf(c);
    }
    gbar();

    // ---- stage 3: 9 sequential levels ----
    const int bases[9]  = {512, 768, 896, 960, 992, 1008, 1016, 1020, 1022};
    const int widths[9] = {256, 128, 64, 32, 16, 8, 4, 2, 1};
#pragma unroll 1
    for (int l = 0; l < 9; l++) {
        const int W = widths[l], base = bases[l];
        gemm_stage(g_h, children + 2 * base, 2 * W, g_Whp, g_G, As, Bs);
        gbar();
        for (int idx = blockIdx.x * NTHR + threadIdx.x; idx < W * HD; idx += NBLK * NTHR) {
            int p = idx / HD, j = idx % HD;
            int t = base + p;
            const float* xx = g_XX + (size_t)t * NBP;
            const float* G0 = g_G + (size_t)(2 * p) * NBP;
            const float* G1 = G0 + NBP;
            float xi = xx[j]          + g_bsum[j];
            float xf = xx[GP + j]     + g_bsum[GP + j];
            float xu = xx[2 * GP + j] + g_bsum[2 * GP + j];
            float g0f = G0[GP + j], g1f = G1[GP + j];
            float i = sigf(xi + G0[j]          + G1[j]);
            float o = sigf(xf + g0f            + g1f);
            float u = sigf(xu + G0[2 * GP + j] + G1[2 * GP + j]);
            float f0 = sigf(xf + g0f);
            float f1 = sigf(xf + g1f);
            int c0 = children[2 * t], c1 = children[2 * t + 1];
            float cc = i * u + f0 * g_c[c0 * HD + j] + f1 * g_c[c1 * HD + j];
            g_c[t * HD + j] = cc;
            g_h[t * HD + j] = o * tanhf(cc);
        }
        gbar();
    }

    // ---- stage 4: logits + log_softmax + per-node loss (warp per node) ----
    {
        int gw = (blockIdx.x * NTHR + threadIdx.x) >> 5;
        int lane = threadIdx.x & 31;
        if (gw < NN) {
            const float* h = g_h + (size_t)gw * HD;
            float a0 = 0.f, a1 = 0.f, a2 = 0.f, a3 = 0.f, a4 = 0.f;
            for (int j = lane; j < HD; j += 32) {
                float hv = h[j];
                const float* w = Wout + j * 5;
                a0 += hv * w[0]; a1 += hv * w[1]; a2 += hv * w[2];
                a3 += hv * w[3]; a4 += hv * w[4];
            }
#pragma unroll
            for (int off = 16; off > 0; off >>= 1) {
                a0 += __shfl_down_sync(0xffffffffu, a0, off);
                a1 += __shfl_down_sync(0xffffffffu, a1, off);
                a2 += __shfl_down_sync(0xffffffffu, a2, off);
                a3 += __shfl_down_sync(0xffffffffu, a3, off);
                a4 += __shfl_down_sync(0xffffffffu, a4, off);
            }
            if (lane == 0) {
                float lg[5] = {a0 + bout[0], a1 + bout[1], a2 + bout[2],
                               a3 + bout[3], a4 + bout[4]};
                float mx = lg[0];
#pragma unroll
                for (int l = 1; l < 5; l++) mx = fmaxf(mx, lg[l]);
                float se = 0.f;
#pragma unroll
                for (int l = 0; l < 5; l++) se += expf(lg[l] - mx);
                float lse = mx + logf(se);
                float* dst = (out_size >= NN * 5) ? (out + (size_t)gw * 5)
                                                  : (g_logp_scratch + (size_t)gw * 5);
#pragma unroll
                for (int l = 0; l < 5; l++) dst[l] = lg[l] - lse;
                g_loss[gw] = -(lg[labels[gw]] - lse);
            }
        }
    }
    gbar();

    // ---- stage 5: loss reduction (block 0) ----
    if (blockIdx.x == 0) {
        float v = 0.f;
        for (int i = threadIdx.x; i < NN; i += NTHR) v += g_loss[i];
        sred[threadIdx.x] = v;
        __syncthreads();
        for (int st = NTHR / 2; st > 0; st >>= 1) {
            if (threadIdx.x < st) sred[threadIdx.x] += sred[threadIdx.x + st];
            __syncthreads();
        }
        if (threadIdx.x == 0) {
            if (out_size > NN * 5)      out[NN * 5] = sred[0];
            else if (out_size < NN * 5) out[0]      = sred[0];
        }
    }
}

// ---------------- launch ----------------
extern "C" void kernel_launch(void* const* d_in, const int* in_sizes, int n_in,
                              void* d_out, int out_size)
{
    const int*   word_ids = (const int*)d_in[0];
    const int*   labels   = (const int*)d_in[1];
    const int*   children = (const int*)d_in[2];
    // d_in[3] children_mask: implied by tree structure
    const float* emb = (const float*)d_in[4];
    const float* Wix = (const float*)d_in[5],  *bix = (const float*)d_in[6];
    const float* Wih = (const float*)d_in[7],  *bih = (const float*)d_in[8];
    const float* Wfx = (const float*)d_in[9],  *bfx = (const float*)d_in[10];
    const float* Wfh = (const float*)d_in[11], *bfh = (const float*)d_in[12];
    const float* Wux = (const float*)d_in[13], *bux = (const float*)d_in[14];
    const float* Wuh = (const float*)d_in[15], *buh = (const float*)d_in[16];
    const float* Wout = (const float*)d_in[17], *bout = (const float*)d_in[18];
    float* out = (float*)d_out;

    pack_w<<<(HD * NBP + 255) / 256, 256>>>(Wix, Wfx, Wux, Wih, Wfh, Wuh,
                                            bix, bfx, bux, bih, bfh, buh);
    mega_kernel<<<NBLK, NTHR>>>(word_ids, labels, children, emb, Wout, bout,
                                out, out_size);
}

// round 5
// speedup vs baseline: 1.9691x; 1.2048x over previous
#include <cuda_runtime.h>
#include <math.h>

#define NN      1023
#define NLEAVES 512
#define HD      300
#define GP      320          // padded per-gate width
#define NBP     960          // 3 * GP = 15 * 64
#define NBLK    296          // 2 blocks/SM on 148 SMs (<=304 on GB300's 152)
#define NTHR    256
#define GSTRIDE (512 * NBP)  // per-split-chunk partial buffer stride

typedef unsigned long long ull;

// ---------------- static device scratch ----------------
__device__ float g_Wxp[HD * NBP];      // packed W_ix|W_fx|W_ux
__device__ float g_Whp[HD * NBP];      // packed W_ih|W_fh|W_uh
__device__ float g_bsum[NBP];          // b_*x + b_*h
__device__ float g_XX[NN * NBP];       // x @ Wxp
__device__ float g_Gs[5 * GSTRIDE];    // split-K partial child GEMM results
__device__ float g_h[NN * HD];
__device__ float g_c[NN * HD];
__device__ float g_loss[NN];
__device__ float g_logp_scratch[NN * 5];
__device__ unsigned g_gen;
__device__ unsigned g_cnt;

// ---------------- f32x2 helpers ----------------
static __device__ __forceinline__ ull pack2(float x, float y) {
    ull r;
    asm("mov.b64 %0, {%1, %2};" : "=l"(r) : "f"(x), "f"(y));
    return r;
}
static __device__ __forceinline__ void unpack2(ull v, float &x, float &y) {
    asm("mov.b64 {%0, %1}, %2;" : "=f"(x), "=f"(y) : "l"(v));
}
static __device__ __forceinline__ void ffma2(ull &d, ull a, ull b) {
    asm("fma.rn.f32x2 %0, %1, %2, %0;" : "+l"(d) : "l"(a), "l"(b));
}
static __device__ __forceinline__ float sigf(float x) {
    return 1.0f / (1.0f + expf(-x));
}

// ---------------- software grid barrier (all NBLK blocks resident) ----------------
static __device__ __forceinline__ void gbar() {
    __threadfence();
    __syncthreads();
    if (threadIdx.x == 0) {
        unsigned gen = *((volatile unsigned*)&g_gen);
        if (atomicAdd(&g_cnt, 1u) == NBLK - 1) {
            g_cnt = 0;
            __threadfence();
            atomicAdd(&g_gen, 1u);   // release
        } else {
            while (*((volatile unsigned*)&g_gen) == gen) { }
        }
        __threadfence();
    }
    __syncthreads();
}

// ---------------- pack weights into [300][960] gate-padded strips ----------------
__global__ void pack_w(const float* __restrict__ Wix, const float* __restrict__ Wfx,
                       const float* __restrict__ Wux, const float* __restrict__ Wih,
                       const float* __restrict__ Wfh, const float* __restrict__ Wuh,
                       const float* __restrict__ bix, const float* __restrict__ bfx,
                       const float* __restrict__ bux, const float* __restrict__ bih,
                       const float* __restrict__ bfh, const float* __restrict__ buh)
{
    int idx = blockIdx.x * blockDim.x + threadIdx.x;
    if (idx < HD * NBP) {
        int k = idx / NBP, c = idx % NBP;
        int g = c / GP, j = c % GP;
        float vx = 0.f, vh = 0.f;
        if (j < HD) {
            const float* wx = (g == 0) ? Wix : (g == 1) ? Wfx : Wux;
            const float* wh = (g == 0) ? Wih : (g == 1) ? Wfh : Wuh;
            vx = wx[k * HD + j];
            vh = wh[k * HD + j];
        }
        g_Wxp[idx] = vx;
        g_Whp[idx] = vh;
    }
    if (idx < NBP) {
        int g = idx / GP, j = idx % GP;
        float v = 0.f;
        if (j < HD) {
            const float* bx = (g == 0) ? bix : (g == 1) ? bfx : bux;
            const float* bh = (g == 0) ? bih : (g == 1) ? bfh : buh;
            v = bx[j] + bh[j];
        }
        g_bsum[idx] = v;
    }
}

// ---------------- stage loaders ----------------
static __device__ __forceinline__ void ld_stage_regs(
    const float* __restrict__ aptr, bool aval,
    const float* __restrict__ bptr, int kb, int akq, int bk,
    float4 &a0, float4 &a1, float4 &b0, float4 &b1)
{
    const float4 z = make_float4(0.f, 0.f, 0.f, 0.f);
    int gk0 = kb + (akq << 2), gk1 = gk0 + 16;
    a0 = (aval && gk0 < HD) ? *(const float4*)(aptr + gk0) : z;
    a1 = (aval && gk1 < HD) ? *(const float4*)(aptr + gk1) : z;
    int gb0 = kb + bk, gb1 = gb0 + 16;
    b0 = (gb0 < HD) ? *(const float4*)(bptr + (size_t)gb0 * NBP) : z;
    b1 = (gb1 < HD) ? *(const float4*)(bptr + (size_t)gb1 * NBP) : z;
}

// ---------------- tiled gathered GEMM stage with split-K --------------------------
// out[c][M x 960](partial) = gather(src,rowIdx)[M x 300] @ B over this chunk's k range
__device__ __noinline__ void gemm_stage(const float* __restrict__ src,
                                        const int* __restrict__ rowIdx, int M,
                                        const float* __restrict__ B,
                                        float* __restrict__ out, int sp, int ostride,
                                        float (&As)[2][32][68],
                                        float (&Bs)[2][32][64])
{
    const int tid = threadIdx.x;
    const int tx = tid & 15, ty = tid >> 4;
    const int am  = tid & 63;
    const int akq = tid >> 6;        // 0..3
    const int bn4 = (tid & 15) << 2;
    const int bk  = tid >> 4;        // 0..15

    const int ntm = (M + 63) >> 6;
    const int ntiles = ntm * 15 * sp;
    const int S = 10;                // stages of BK=32 over K=300

    for (int t = blockIdx.x; t < ntiles; t += NBLK) {
        const int c  = t % sp;
        const int tt = t / sp;
        const int m0 = (tt / 15) << 6;
        const int n0 = (tt % 15) << 6;
        const int s0 = (c * S) / sp;
        const int s1 = ((c + 1) * S) / sp;

        const bool aval = (m0 + am < M);
        const int  arow = aval ? rowIdx[m0 + am] : 0;
        const float* __restrict__ aptr = src + (size_t)arow * HD;
        const float* __restrict__ bptr = B + n0 + bn4;

        const bool act = (m0 + (ty << 2) < M);

        float4 a0, a1, b0, b1;
        ld_stage_regs(aptr, aval, bptr, s0 << 5, akq, bk, a0, a1, b0, b1);
        {
            int ka = akq << 2;
            As[0][ka + 0][am] = a0.x; As[0][ka + 1][am] = a0.y;
            As[0][ka + 2][am] = a0.z; As[0][ka + 3][am] = a0.w;
            As[0][16 + ka + 0][am] = a1.x; As[0][16 + ka + 1][am] = a1.y;
            As[0][16 + ka + 2][am] = a1.z; As[0][16 + ka + 3][am] = a1.w;
            *(float4*)&Bs[0][bk][bn4]      = b0;
            *(float4*)&Bs[0][bk + 16][bn4] = b1;
        }
        __syncthreads();

        ull acc[4][2];
#pragma unroll
        for (int i = 0; i < 4; i++) { acc[i][0] = pack2(0.f, 0.f); acc[i][1] = pack2(0.f, 0.f); }

        for (int s = s0; s < s1; s++) {
            const int p = (s - s0) & 1;

            if (s + 1 < s1)
                ld_stage_regs(aptr, aval, bptr, (s + 1) << 5, akq, bk, a0, a1, b0, b1);

            if (act) {
                float4 a_c = *(const float4*)&As[p][0][ty << 2];
                ulonglong2 b_c = *(const ulonglong2*)&Bs[p][0][tx << 2];
#pragma unroll
                for (int k = 0; k < 32; k++) {
                    float4 a_n;
                    ulonglong2 b_n;
                    if (k < 31) {
                        a_n = *(const float4*)&As[p][k + 1][ty << 2];
                        b_n = *(const ulonglong2*)&Bs[p][k + 1][tx << 2];
                    } else {
                        a_n = make_float4(0.f, 0.f, 0.f, 0.f);
                        b_n.x = 0; b_n.y = 0;
                    }
                    ull ap;
                    ap = pack2(a_c.x, a_c.x); ffma2(acc[0][0], ap, b_c.x); ffma2(acc[0][1], ap, b_c.y);
                    ap = pack2(a_c.y, a_c.y); ffma2(acc[1][0], ap, b_c.x); ffma2(acc[1][1], ap, b_c.y);
                    ap = pack2(a_c.z, a_c.z); ffma2(acc[2][0], ap, b_c.x); ffma2(acc[2][1], ap, b_c.y);
                    ap = pack2(a_c.w, a_c.w); ffma2(acc[3][0], ap, b_c.x); ffma2(acc[3][1], ap, b_c.y);
                    a_c = a_n; b_c = b_n;
                }
            }

            if (s + 1 < s1) {
                const int q = p ^ 1;
                int ka = akq << 2;
                As[q][ka + 0][am] = a0.x; As[q][ka + 1][am] = a0.y;
                As[q][ka + 2][am] = a0.z; As[q][ka + 3][am] = a0.w;
                As[q][16 + ka + 0][am] = a1.x; As[q][16 + ka + 1][am] = a1.y;
                As[q][16 + ka + 2][am] = a1.z; As[q][16 + ka + 3][am] = a1.w;
                *(float4*)&Bs[q][bk][bn4]      = b0;
                *(float4*)&Bs[q][bk + 16][bn4] = b1;
            }
            __syncthreads();
        }

        if (act) {
            float* __restrict__ ob = out + (size_t)c * ostride;
#pragma unroll
            for (int i = 0; i < 4; i++) {
                int gm = m0 + (ty << 2) + i;
                if (gm < M) {
                    float x0, x1, x2, x3;
                    unpack2(acc[i][0], x0, x1);
                    unpack2(acc[i][1], x2, x3);
                    *(float4*)&ob[(size_t)gm * NBP + n0 + (tx << 2)] =
                        make_float4(x0, x1, x2, x3);
                }
            }
        }
    }
}

// ---------------- persistent mega-kernel ----------------
__global__ __launch_bounds__(NTHR, 2) void mega_kernel(
    const int* __restrict__ word_ids, const int* __restrict__ labels,
    const int* __restrict__ children, const float* __restrict__ emb,
    const float* __restrict__ Wout, const float* __restrict__ bout,
    float* __restrict__ out, int out_size)
{
    __shared__ float As[2][32][68];
    __shared__ __align__(16) float Bs[2][32][64];
    __shared__ float sred[NTHR];

    // ---- stage 1: prologue GEMM  XX = emb[word_ids] @ Wxp ----
    gemm_stage(emb, word_ids, NN, g_Wxp, g_XX, 1, 0, As, Bs);
    gbar();

    // ---- stage 2: leaves ----
    for (int idx = blockIdx.x * NTHR + threadIdx.x; idx < NLEAVES * HD; idx += NBLK * NTHR) {
        int t = idx / HD, j = idx % HD;
        const float* xx = g_XX + (size_t)t * NBP;
        float i = sigf(xx[j]          + g_bsum[j]);
        float o = sigf(xx[GP + j]     + g_bsum[GP + j]);
        float u = sigf(xx[2 * GP + j] + g_bsum[2 * GP + j]);
        float c = i * u;
        g_c[t * HD + j] = c;
        g_h[t * HD + j] = o * tanhf(c);
    }
    gbar();

    // ---- stage 3: 9 sequential levels ----
    const int bases[9]  = {512, 768, 896, 960, 992, 1008, 1016, 1020, 1022};
    const int widths[9] = {256, 128, 64, 32, 16, 8, 4, 2, 1};
    const int splits[9] = {2, 4, 5, 5, 5, 5, 5, 5, 5};
#pragma unroll 1
    for (int l = 0; l < 9; l++) {
        const int W = widths[l], base = bases[l], sp = splits[l];
        gemm_stage(g_h, children + 2 * base, 2 * W, g_Whp, g_Gs, sp, GSTRIDE, As, Bs);
        gbar();
        for (int idx = blockIdx.x * NTHR + threadIdx.x; idx < W * HD; idx += NBLK * NTHR) {
            int p = idx / HD, j = idx % HD;
            int t = base + p;
            const float* xx = g_XX + (size_t)t * NBP;
            float s_i = 0.f, s_u = 0.f, g0f = 0.f, g1f = 0.f;
#pragma unroll 1
            for (int c = 0; c < sp; c++) {
                const float* G0 = g_Gs + (size_t)c * GSTRIDE + (size_t)(2 * p) * NBP;
                const float* G1 = G0 + NBP;
                s_i += G0[j] + G1[j];
                g0f += G0[GP + j];
                g1f += G1[GP + j];
                s_u += G0[2 * GP + j] + G1[2 * GP + j];
            }
            float xi = xx[j]          + g_bsum[j];
            float xf = xx[GP + j]     + g_bsum[GP + j];
            float xu = xx[2 * GP + j] + g_bsum[2 * GP + j];
            float i = sigf(xi + s_i);
            float o = sigf(xf + g0f + g1f);
            float u = sigf(xu + s_u);
            float f0 = sigf(xf + g0f);
            float f1 = sigf(xf + g1f);
            int c0 = children[2 * t], c1 = children[2 * t + 1];
            float cc = i * u + f0 * g_c[c0 * HD + j] + f1 * g_c[c1 * HD + j];
            g_c[t * HD + j] = cc;
            g_h[t * HD + j] = o * tanhf(cc);
        }
        gbar();
    }

    // ---- stage 4: logits + log_softmax + per-node loss (warp per node) ----
    {
        int gw = (blockIdx.x * NTHR + threadIdx.x) >> 5;
        int lane = threadIdx.x & 31;
        if (gw < NN) {
            const float* h = g_h + (size_t)gw * HD;
            float a0 = 0.f, a1 = 0.f, a2 = 0.f, a3 = 0.f, a4 = 0.f;
            for (int j = lane; j < HD; j += 32) {
                float hv = h[j];
                const float* w = Wout + j * 5;
                a0 += hv * w[0]; a1 += hv * w[1]; a2 += hv * w[2];
                a3 += hv * w[3]; a4 += hv * w[4];
            }
#pragma unroll
            for (int off = 16; off > 0; off >>= 1) {
                a0 += __shfl_down_sync(0xffffffffu, a0, off);
                a1 += __shfl_down_sync(0xffffffffu, a1, off);
                a2 += __shfl_down_sync(0xffffffffu, a2, off);
                a3 += __shfl_down_sync(0xffffffffu, a3, off);
                a4 += __shfl_down_sync(0xffffffffu, a4, off);
            }
            if (lane == 0) {
                float lg[5] = {a0 + bout[0], a1 + bout[1], a2 + bout[2],
                               a3 + bout[3], a4 + bout[4]};
                float mx = lg[0];
#pragma unroll
                for (int l = 1; l < 5; l++) mx = fmaxf(mx, lg[l]);
                float se = 0.f;
#pragma unroll
                for (int l = 0; l < 5; l++) se += expf(lg[l] - mx);
                float lse = mx + logf(se);
                float* dst = (out_size >= NN * 5) ? (out + (size_t)gw * 5)
                                                  : (g_logp_scratch + (size_t)gw * 5);
#pragma unroll
                for (int l = 0; l < 5; l++) dst[l] = lg[l] - lse;
                g_loss[gw] = -(lg[labels[gw]] - lse);
            }
        }
    }
    gbar();

    // ---- stage 5: loss reduction (block 0) ----
    if (blockIdx.x == 0) {
        float v = 0.f;
        for (int i = threadIdx.x; i < NN; i += NTHR) v += g_loss[i];
        sred[threadIdx.x] = v;
        __syncthreads();
        for (int st = NTHR / 2; st > 0; st >>= 1) {
            if (threadIdx.x < st) sred[threadIdx.x] += sred[threadIdx.x + st];
            __syncthreads();
        }
        if (threadIdx.x == 0) {
            if (out_size > NN * 5)      out[NN * 5] = sred[0];
            else if (out_size < NN * 5) out[0]      = sred[0];
        }
    }
}

// ---------------- launch ----------------
extern "C" void kernel_launch(void* const* d_in, const int* in_sizes, int n_in,
                              void* d_out, int out_size)
{
    const int*   word_ids = (const int*)d_in[0];
    const int*   labels   = (const int*)d_in[1];
    const int*   children = (const int*)d_in[2];
    const float* emb = (const float*)d_in[4];
    const float* Wix = (const float*)d_in[5],  *bix = (const float*)d_in[6];
    const float* Wih = (const float*)d_in[7],  *bih = (const float*)d_in[8];
    const float* Wfx = (const float*)d_in[9],  *bfx = (const float*)d_in[10];
    const float* Wfh = (const float*)d_in[11], *bfh = (const float*)d_in[12];
    const float* Wux = (const float*)d_in[13], *bux = (const float*)d_in[14];
    const float* Wuh = (const float*)d_in[15], *buh = (const float*)d_in[16];
    const float* Wout = (const float*)d_in[17], *bout = (const float*)d_in[18];
    float* out = (float*)d_out;

    pack_w<<<(HD * NBP + 255) / 256, 256>>>(Wix, Wfx, Wux, Wih, Wfh, Wuh,
                                            bix, bfx, bux, bih, bfh, buh);
    mega_kernel<<<NBLK, NTHR>>>(word_ids, labels, children, emb, Wout, bout,
                                out, out_size);
}